// round 15
// baseline (speedup 1.0000x reference)
#include <cuda_runtime.h>
#include <cuda_fp16.h>
#include <math.h>
#include <stdint.h>

#define N_NODES 2048
#define BATCH   32
#define HIDDEN  64
#define C_IN    66                 // DIM_IN + HIDDEN
#define BC      2112               // BATCH * C_IN
#define NPAD    2176               // BC padded to multiple of 128
#define IN3     198                // 3 * C_IN
#define GATE_OUT 128
#define UPD_OUT  64

// ---------------- device scratch (static: no allocations allowed) ----------
__device__ __half g_Ah [N_NODES * N_NODES];
__device__ __half g_T0 [NPAD * N_NODES];    // X0T, then (in-place) C0T
__device__ __half g_T1 [NPAD * N_NODES];    // X1T / C1T
__device__ __half g_T2 [NPAD * N_NODES];    // Y2T / Y4T
__device__ float g_r [BATCH * N_NODES * HIDDEN];
__device__ float g_Wg2[IN3 * GATE_OUT];     // folded gate weights
__device__ float g_Wu2[IN3 * UPD_OUT];      // folded update weights

__device__ __forceinline__ uint32_t smem_to_u32(const void* p) {
    uint32_t a;
    asm("{ .reg .u64 t; cvta.to.shared.u64 t, %1; cvt.u32.u64 %0, t; }" : "=r"(a) : "l"(p));
    return a;
}
__device__ __forceinline__ void mma_fp16(float* c, const uint32_t* a, const uint32_t* b) {
    asm volatile(
        "mma.sync.aligned.m16n8k16.row.col.f32.f16.f16.f32 "
        "{%0,%1,%2,%3}, {%4,%5,%6,%7}, {%8,%9}, {%0,%1,%2,%3};"
        : "+f"(c[0]), "+f"(c[1]), "+f"(c[2]), "+f"(c[3])
        : "r"(a[0]), "r"(a[1]), "r"(a[2]), "r"(a[3]), "r"(b[0]), "r"(b[1]));
}
__device__ __forceinline__ void ldsm4(uint32_t* r, uint32_t addr) {
    asm volatile("ldmatrix.sync.aligned.m8n8.x4.shared.b16 {%0,%1,%2,%3}, [%4];"
                 : "=r"(r[0]), "=r"(r[1]), "=r"(r[2]), "=r"(r[3]) : "r"(addr));
}
__device__ __forceinline__ void cp16(uint32_t daddr, const void* g) {
    asm volatile("cp.async.cg.shared.global [%0], [%1], 16;" :: "r"(daddr), "l"(g));
}
__device__ __forceinline__ unsigned long long pack_dup(float b) {
    unsigned long long r;
    asm("mov.b64 %0, {%1, %1};" : "=l"(r) : "f"(b));
    return r;
}
__device__ __forceinline__ void ffma2(unsigned long long& d,
                                      unsigned long long a,
                                      unsigned long long b) {
    asm("fma.rn.f32x2 %0, %1, %2, %0;" : "+l"(d) : "l"(a), "l"(b));
}

// ---------------- K1: fused prep: supports | packT | padT0 | wfold ---------
__global__ void __launch_bounds__(256)
prep_kernel(const float* __restrict__ E, const float* __restrict__ x,
            const float* __restrict__ st, const float* __restrict__ Wg,
            const float* __restrict__ Wu) {
    int blk = blockIdx.x;
    int t = threadIdx.x;

    if (blk < 2048) {                       // ---- supports ----
        int n = blk;
        float e[10];
#pragma unroll
        for (int c = 0; c < 10; c++) e[c] = E[n * 10 + c];
        float vals[8];
        float vmax = 0.0f;
#pragma unroll
        for (int j = 0; j < 8; j++) {
            int m = j * 256 + t;
            float s = 0.0f;
#pragma unroll
            for (int c = 0; c < 10; c++) s = fmaf(e[c], E[m * 10 + c], s);
            s = fmaxf(s, 0.0f);
            vals[j] = s;
            vmax = fmaxf(vmax, s);
        }
        __shared__ float red[256];
        red[t] = vmax; __syncthreads();
        for (int s = 128; s > 0; s >>= 1) {
            if (t < s) red[t] = fmaxf(red[t], red[t + s]);
            __syncthreads();
        }
        vmax = red[0]; __syncthreads();
        float lsum = 0.0f;
#pragma unroll
        for (int j = 0; j < 8; j++) { vals[j] = expf(vals[j] - vmax); lsum += vals[j]; }
        red[t] = lsum; __syncthreads();
        for (int s = 128; s > 0; s >>= 1) {
            if (t < s) red[t] += red[t + s];
            __syncthreads();
        }
        float inv = 1.0f / red[0];
#pragma unroll
        for (int j = 0; j < 8; j++)
            g_Ah[(size_t)n * N_NODES + j * 256 + t] = __float2half_rn(vals[j] * inv);

    } else if (blk < 4096) {                // ---- packT ----
        __shared__ float tile[2][16][68];
        int p = blk - 2048;                 // 2048 = 32 b * 64 chunks(32 nodes)
        int b = p >> 6;
        int n0 = (p & 63) * 32;
        int sub = t >> 7;
        int t2 = t & 127;
        int nb = n0 + sub * 16;

        for (int idx = t2; idx < 1024; idx += 128) {
            int rr = idx >> 6, c = idx & 63;
            tile[sub][rr][2 + c] = st[((size_t)b * N_NODES + nb + rr) * 64 + c];
        }
        if (t2 < 32) {
            int rr = t2 >> 1, c = t2 & 1;
            tile[sub][rr][c] = x[((size_t)b * N_NODES + nb + rr) * 2 + c];
        }
        __syncthreads();
        if (t2 < C_IN) {
            __half h[16];
#pragma unroll
            for (int rr = 0; rr < 16; rr++) h[rr] = __float2half_rn(tile[sub][rr][t2]);
            size_t off = (size_t)(b * C_IN + t2) * N_NODES + nb;
            *(uint4*)(g_T0 + off)     = *(uint4*)&h[0];
            *(uint4*)(g_T0 + off + 8) = *(uint4*)&h[8];
        }

    } else if (blk < 4160) {                // ---- padT0 ----
        int idx = (blk - 4096) * 256 + t;
        if (idx < (NPAD - BC) * N_NODES / 8) {
            size_t off = (size_t)BC * N_NODES + (size_t)idx * 8;
            *(uint4*)(g_T0 + off) = make_uint4(0, 0, 0, 0);
        }

    } else {                                // ---- wfold ----
        int idx = (blk - 4160) * 256 + t;
        if (idx < C_IN * GATE_OUT) {
            int c = idx / GATE_OUT, o = idx - c * GATE_OUT;
            float w0 = Wg[(c)            * GATE_OUT + o];
            float w1 = Wg[(C_IN + c)     * GATE_OUT + o];
            float w2 = Wg[(2 * C_IN + c) * GATE_OUT + o];
            g_Wg2[(c)            * GATE_OUT + o] = w0 - w2;
            g_Wg2[(C_IN + c)     * GATE_OUT + o] = w1;
            g_Wg2[(2 * C_IN + c) * GATE_OUT + o] = 2.f * w2;
        }
        if (idx < C_IN * UPD_OUT) {
            int c = idx / UPD_OUT, o = idx - c * UPD_OUT;
            float w0 = Wu[(c)            * UPD_OUT + o];
            float w1 = Wu[(C_IN + c)     * UPD_OUT + o];
            float w2 = Wu[(2 * C_IN + c) * UPD_OUT + o];
            g_Wu2[(c)            * UPD_OUT + o] = w0 - w2;
            g_Wu2[(C_IN + c)     * UPD_OUT + o] = w1;
            g_Wu2[(2 * C_IN + c) * UPD_OUT + o] = 2.f * w2;
        }
    }
}

// ---------------- HMMA GEMM: raw D = A @ B^T, fp16 in, fp16 T out ----------
__global__ void __launch_bounds__(256, 1)
mma_gemm(const __half* __restrict__ Ah, const __half* __restrict__ B,
         __half* __restrict__ CT) {
    extern __shared__ char smem[];
    const uint32_t sb = smem_to_u32(smem);
    const int tid = threadIdx.x, wid = tid >> 5, lane = tid & 31;
    const int wr = wid >> 1, wc = wid & 1;            // warp tile: 64x64
    const int m0 = blockIdx.y * 256, n0 = blockIdx.x * 128;

    const __half* srcA = Ah + (size_t)m0 * N_NODES;
    const __half* srcB = B  + (size_t)n0 * N_NODES;

    float acc[4][8][4];
#pragma unroll
    for (int i = 0; i < 4; i++)
#pragma unroll
        for (int j = 0; j < 8; j++)
#pragma unroll
            for (int k = 0; k < 4; k++) acc[i][j][k] = 0.f;

#define COPY_CHUNK(k0, bufi) do {                                             \
        uint32_t _b = sb + (bufi) * 73728;                                    \
        _Pragma("unroll")                                                     \
        for (int _u = 0; _u < 8; _u++) {          /* A: 8 units */            \
            int _unit = _u * 256 + tid;                                       \
            int _row = _unit >> 3, _q = _unit & 7;                            \
            int _sl = _q >> 1, _hf = _q & 1;                                  \
            cp16(_b + _sl * 12288 + _row * 48 + _hf * 16,                     \
                 srcA + (size_t)_row * N_NODES + (k0) + _sl * 16 + _hf * 8);  \
        }                                                                     \
        _Pragma("unroll")                                                     \
        for (int _u = 0; _u < 4; _u++) {          /* B: 4 units */            \
            int _unit = _u * 256 + tid;                                       \
            int _row = _unit >> 3, _q = _unit & 7;                            \
            int _sl = _q >> 1, _hf = _q & 1;                                  \
            cp16(_b + 49152 + _sl * 6144 + _row * 48 + _hf * 16,              \
                 srcB + (size_t)_row * N_NODES + (k0) + _sl * 16 + _hf * 8);  \
        }                                                                     \
        asm volatile("cp.async.commit_group;");                               \
    } while (0)

    COPY_CHUNK(0, 0);

    const int NCHUNK = N_NODES / 64;   // 32
    for (int c = 0; c < NCHUNK; c++) {
        int buf = c & 1;
        if (c + 1 < NCHUNK) {
            COPY_CHUNK((c + 1) * 64, buf ^ 1);
            asm volatile("cp.async.wait_group 1;");
        } else {
            asm volatile("cp.async.wait_group 0;");
        }
        __syncthreads();

        uint32_t base = sb + buf * 73728;

#pragma unroll
        for (int s = 0; s < 4; s++) {
            uint32_t a_f[4][4], b_f[4][4];
            int a_roff = (wr * 64 + (lane & 15)) * 48 + (lane >> 4) * 16 + s * 12288;
#pragma unroll
            for (int mt = 0; mt < 4; mt++)
                ldsm4(a_f[mt], base + a_roff + mt * 768);
            int q = lane >> 3, rl = lane & 7;
            int b_roff = (wc * 64 + (q >> 1) * 8 + rl) * 48 + (q & 1) * 16 + s * 6144;
#pragma unroll
            for (int p = 0; p < 4; p++)
                ldsm4(b_f[p], base + 49152 + b_roff + p * 768);
#pragma unroll
            for (int mt = 0; mt < 4; mt++)
#pragma unroll
                for (int nt = 0; nt < 8; nt++)
                    mma_fp16(acc[mt][nt], a_f[mt], &b_f[nt >> 1][(nt & 1) * 2]);
        }
        __syncthreads();
    }
#undef COPY_CHUNK

    // ---- epilogue: smem transpose -> fp16 [n][node] (coalesced) ----
    const int frow = lane >> 2, fcol = (lane & 3) * 2;
    float* Ct = (float*)smem;          // [128][264] fp32 = 135168B
    __syncthreads();
#pragma unroll
    for (int mt = 0; mt < 4; mt++) {
#pragma unroll
        for (int nt = 0; nt < 8; nt++) {
            int mloc = wr * 64 + mt * 16 + frow;
            int nloc = wc * 64 + nt * 8 + fcol;
            Ct[(nloc + 0) * 264 + mloc]     = acc[mt][nt][0];
            Ct[(nloc + 1) * 264 + mloc]     = acc[mt][nt][1];
            Ct[(nloc + 0) * 264 + mloc + 8] = acc[mt][nt][2];
            Ct[(nloc + 1) * 264 + mloc + 8] = acc[mt][nt][3];
        }
    }
    __syncthreads();
    for (int it = 0; it < 16; it++) {
        int nloc = it * 8 + wid;
#pragma unroll
        for (int j = 0; j < 2; j++) {
            int mloc = lane * 4 + j * 128;
            float4 v = *(float4*)&Ct[nloc * 264 + mloc];
            __half h[4];
            h[0] = __float2half_rn(v.x);
            h[1] = __float2half_rn(v.y);
            h[2] = __float2half_rn(v.z);
            h[3] = __float2half_rn(v.w);
            size_t off = (size_t)(n0 + nloc) * N_NODES + m0 + mloc;
            *(uint2*)(CT + off) = *(uint2*)h;
        }
    }
}

// ---------------- K4: gate projection, 64 rows/block, 2 outputs/thread -----
// Block = (b, 64 nodes). thread: oh=t&63 -> outputs 2*oh,2*oh+1; hh=t>>6 ->
// rows hh*32..hh*32+31. Writes C0T in place (block owns its T0 slice).
__global__ void __launch_bounds__(128)
gate_kernel(const float* __restrict__ x, const float* __restrict__ st,
            const float* __restrict__ bg) {
    __shared__ float in_s[IN3][66];    // stride 66 floats, pairs 8B-aligned
    int row0 = blockIdx.x * 64;
    int b = row0 >> 11, n0 = row0 & 2047;
    int t = threadIdx.x;

    const __half* TP[3] = { g_T0, g_T1, g_T2 };

    for (int idx = t; idx < 64 * IN3; idx += 128) {
        int rr = idx & 63, i = idx >> 6;
        int k = i / C_IN, c = i - k * C_IN;
        in_s[i][rr] = __half2float(TP[k][(size_t)(b * C_IN + c) * N_NODES + n0 + rr]);
    }
    __syncthreads();

    int oh = t & 63, hh = t >> 6;
    int o0 = oh * 2;
    int rbase = hh * 32;
    unsigned long long acc2[2][16];
#pragma unroll
    for (int u = 0; u < 2; u++)
#pragma unroll
        for (int pp = 0; pp < 16; pp++) acc2[u][pp] = 0ULL;

    for (int i = 0; i < IN3; i++) {
        float2 w2 = *(const float2*)&g_Wg2[i * GATE_OUT + o0];
        unsigned long long wd0 = pack_dup(w2.x);
        unsigned long long wd1 = pack_dup(w2.y);
#pragma unroll
        for (int pp = 0; pp < 16; pp++) {
            unsigned long long v = *(const unsigned long long*)&in_s[i][rbase + pp * 2];
            ffma2(acc2[0][pp], v, wd0);
            ffma2(acc2[1][pp], v, wd1);
        }
    }

#pragma unroll
    for (int u = 0; u < 2; u++) {
        int o = o0 + u;
        float bias = bg[o];
        __half c32[32];
#pragma unroll
        for (int pp = 0; pp < 16; pp++) {
            float2 f = *(float2*)&acc2[u][pp];
#pragma unroll
            for (int h = 0; h < 2; h++) {
                int rr = rbase + pp * 2 + h;
                int row = row0 + rr;
                float v = 1.0f / (1.0f + expf(-((h ? f.y : f.x) + bias)));
                if (o < 64) {
                    c32[pp * 2 + h] = __float2half_rn(v * st[row * 64 + o]);
                } else {
                    g_r[row * 64 + (o - 64)] = v;
                }
            }
        }
        if (o < 64) {
            size_t off = (size_t)(b * C_IN + 2 + o) * N_NODES + n0 + rbase;
#pragma unroll
            for (int q = 0; q < 4; q++)
                *(uint4*)(g_T0 + off + q * 8) = *(uint4*)&c32[q * 8];
            if (o < 2) {
                __half xh[32];
#pragma unroll
                for (int rr = 0; rr < 32; rr++)
                    xh[rr] = __float2half_rn(x[(row0 + rbase + rr) * 2 + o]);
                size_t off2 = (size_t)(b * C_IN + o) * N_NODES + n0 + rbase;
#pragma unroll
                for (int q = 0; q < 4; q++)
                    *(uint4*)(g_T0 + off2 + q * 8) = *(uint4*)&xh[q * 8];
            }
        }
    }
}

// ---------------- K5: update projection, 64 rows/block, 2 outputs/thread ---
// thread: oh=t&31 -> outputs 2*oh,2*oh+1; hh=t>>5 -> rows hh*16..hh*16+15.
__global__ void __launch_bounds__(128)
update_kernel(const float* __restrict__ st, const float* __restrict__ bu,
              float* __restrict__ out) {
    __shared__ float in_s[IN3][66];
    int row0 = blockIdx.x * 64;
    int b = row0 >> 11, n0 = row0 & 2047;
    int t = threadIdx.x;

    const __half* TP[3] = { g_T0, g_T1, g_T2 };

    for (int idx = t; idx < 64 * IN3; idx += 128) {
        int rr = idx & 63, i = idx >> 6;
        int k = i / C_IN, c = i - k * C_IN;
        in_s[i][rr] = __half2float(TP[k][(size_t)(b * C_IN + c) * N_NODES + n0 + rr]);
    }
    __syncthreads();

    int oh = t & 31, hh = t >> 5;
    int o0 = oh * 2;
    int rbase = hh * 16;
    unsigned long long acc2[2][8];
#pragma unroll
    for (int u = 0; u < 2; u++)
#pragma unroll
        for (int pp = 0; pp < 8; pp++) acc2[u][pp] = 0ULL;

    for (int i = 0; i < IN3; i++) {
        float2 w2 = *(const float2*)&g_Wu2[i * UPD_OUT + o0];
        unsigned long long wd0 = pack_dup(w2.x);
        unsigned long long wd1 = pack_dup(w2.y);
#pragma unroll
        for (int pp = 0; pp < 8; pp++) {
            unsigned long long v = *(const unsigned long long*)&in_s[i][rbase + pp * 2];
            ffma2(acc2[0][pp], v, wd0);
            ffma2(acc2[1][pp], v, wd1);
        }
    }

#pragma unroll
    for (int u = 0; u < 2; u++) {
        int o = o0 + u;
        float bias = bu[o];
#pragma unroll
        for (int pp = 0; pp < 8; pp++) {
            float2 f = *(float2*)&acc2[u][pp];
#pragma unroll
            for (int h = 0; h < 2; h++) {
                int row = row0 + rbase + pp * 2 + h;
                float hc = tanhf((h ? f.y : f.x) + bias);
                float rv = g_r[row * 64 + o];
                float sv = st[row * 64 + o];
                out[row * 64 + o] = rv * sv + (1.0f - rv) * hc;
            }
        }
    }
}

// ---------------- launch ----------------------------------------------------
extern "C" void kernel_launch(void* const* d_in, const int* in_sizes, int n_in,
                              void* d_out, int out_size) {
    const float* x  = (const float*)d_in[0];
    const float* st = (const float*)d_in[1];
    const float* E  = (const float*)d_in[2];
    const float* Wg = (const float*)d_in[3];
    const float* bg = (const float*)d_in[4];
    const float* Wu = (const float*)d_in[5];
    const float* bu = (const float*)d_in[6];
    float* out = (float*)d_out;

    __half *pAh, *pT0, *pT1, *pT2;
    cudaGetSymbolAddress((void**)&pAh, g_Ah);
    cudaGetSymbolAddress((void**)&pT0, g_T0);
    cudaGetSymbolAddress((void**)&pT1, g_T1);
    cudaGetSymbolAddress((void**)&pT2, g_T2);

    const int SMEM_BYTES = 2 * 73728;   // 147456 (epilogue Ct uses 135168)
    cudaFuncSetAttribute(mma_gemm, cudaFuncAttributeMaxDynamicSharedMemorySize, SMEM_BYTES);

    dim3 gg(NPAD / 128, N_NODES / 256);   // (17, 8) = 136 CTAs, single wave

    prep_kernel<<<4193, 256>>>(E, x, st, Wg, Wu);

    // gate gconv (folded): X1T = (A X0)T ; Y2T = (A X1)T
    mma_gemm<<<gg, 256, SMEM_BYTES>>>(pAh, pT0, pT1);
    mma_gemm<<<gg, 256, SMEM_BYTES>>>(pAh, pT1, pT2);

    gate_kernel<<<(BATCH * N_NODES) / 64, 128>>>(x, st, bg);  // C0T in place

    // update gconv (folded): C1T = (A C0)T ; Y4T = (A C1)T
    mma_gemm<<<gg, 256, SMEM_BYTES>>>(pAh, pT0, pT1);
    mma_gemm<<<gg, 256, SMEM_BYTES>>>(pAh, pT1, pT2);

    update_kernel<<<(BATCH * N_NODES) / 64, 128>>>(st, bu, out);
}

// round 16
// speedup vs baseline: 1.4108x; 1.4108x over previous
#include <cuda_runtime.h>
#include <cuda_fp16.h>
#include <math.h>
#include <stdint.h>

#define N_NODES 2048
#define BATCH   32
#define HIDDEN  64
#define C_IN    66                 // DIM_IN + HIDDEN
#define BC      2112               // BATCH * C_IN
#define NPAD    2176               // BC padded to multiple of 128
#define IN3     198                // 3 * C_IN
#define KPAD    208                // IN3 padded to multiple of 16
#define GATE_OUT 128
#define UPD_OUT  64

// ---------------- device scratch (static: no allocations allowed) ----------
__device__ __half g_Ah [N_NODES * N_NODES];
__device__ __half g_T0 [NPAD * N_NODES];    // X0T, then (in-place) C0T
__device__ __half g_T1 [NPAD * N_NODES];    // X1T / C1T
__device__ __half g_T2 [NPAD * N_NODES];    // Y2T / Y4T
__device__ float g_r [BATCH * N_NODES * HIDDEN];
__device__ float g_Wg2[IN3 * GATE_OUT];     // folded gate weights
__device__ float g_Wu2[IN3 * UPD_OUT];      // folded update weights

__device__ __forceinline__ uint32_t smem_to_u32(const void* p) {
    uint32_t a;
    asm("{ .reg .u64 t; cvta.to.shared.u64 t, %1; cvt.u32.u64 %0, t; }" : "=r"(a) : "l"(p));
    return a;
}
__device__ __forceinline__ void mma_fp16(float* c, const uint32_t* a, const uint32_t* b) {
    asm volatile(
        "mma.sync.aligned.m16n8k16.row.col.f32.f16.f16.f32 "
        "{%0,%1,%2,%3}, {%4,%5,%6,%7}, {%8,%9}, {%0,%1,%2,%3};"
        : "+f"(c[0]), "+f"(c[1]), "+f"(c[2]), "+f"(c[3])
        : "r"(a[0]), "r"(a[1]), "r"(a[2]), "r"(a[3]), "r"(b[0]), "r"(b[1]));
}
__device__ __forceinline__ void ldsm4(uint32_t* r, uint32_t addr) {
    asm volatile("ldmatrix.sync.aligned.m8n8.x4.shared.b16 {%0,%1,%2,%3}, [%4];"
                 : "=r"(r[0]), "=r"(r[1]), "=r"(r[2]), "=r"(r[3]) : "r"(addr));
}
__device__ __forceinline__ void ldsm4t(uint32_t* r, uint32_t addr) {
    asm volatile("ldmatrix.sync.aligned.m8n8.x4.trans.shared.b16 {%0,%1,%2,%3}, [%4];"
                 : "=r"(r[0]), "=r"(r[1]), "=r"(r[2]), "=r"(r[3]) : "r"(addr));
}
__device__ __forceinline__ void cp16(uint32_t daddr, const void* g) {
    asm volatile("cp.async.cg.shared.global [%0], [%1], 16;" :: "r"(daddr), "l"(g));
}

// ---------------- K1: fused prep: supports | packT | padT0 | wfold ---------
__global__ void __launch_bounds__(256)
prep_kernel(const float* __restrict__ E, const float* __restrict__ x,
            const float* __restrict__ st, const float* __restrict__ Wg,
            const float* __restrict__ Wu) {
    int blk = blockIdx.x;
    int t = threadIdx.x;

    if (blk < 2048) {                       // ---- supports ----
        int n = blk;
        float e[10];
#pragma unroll
        for (int c = 0; c < 10; c++) e[c] = E[n * 10 + c];
        float vals[8];
        float vmax = 0.0f;
#pragma unroll
        for (int j = 0; j < 8; j++) {
            int m = j * 256 + t;
            float s = 0.0f;
#pragma unroll
            for (int c = 0; c < 10; c++) s = fmaf(e[c], E[m * 10 + c], s);
            s = fmaxf(s, 0.0f);
            vals[j] = s;
            vmax = fmaxf(vmax, s);
        }
        __shared__ float red[256];
        red[t] = vmax; __syncthreads();
        for (int s = 128; s > 0; s >>= 1) {
            if (t < s) red[t] = fmaxf(red[t], red[t + s]);
            __syncthreads();
        }
        vmax = red[0]; __syncthreads();
        float lsum = 0.0f;
#pragma unroll
        for (int j = 0; j < 8; j++) { vals[j] = expf(vals[j] - vmax); lsum += vals[j]; }
        red[t] = lsum; __syncthreads();
        for (int s = 128; s > 0; s >>= 1) {
            if (t < s) red[t] += red[t + s];
            __syncthreads();
        }
        float inv = 1.0f / red[0];
#pragma unroll
        for (int j = 0; j < 8; j++)
            g_Ah[(size_t)n * N_NODES + j * 256 + t] = __float2half_rn(vals[j] * inv);

    } else if (blk < 4096) {                // ---- packT ----
        __shared__ float tile[2][16][68];
        int p = blk - 2048;
        int b = p >> 6;
        int n0 = (p & 63) * 32;
        int sub = t >> 7;
        int t2 = t & 127;
        int nb = n0 + sub * 16;

        for (int idx = t2; idx < 1024; idx += 128) {
            int rr = idx >> 6, c = idx & 63;
            tile[sub][rr][2 + c] = st[((size_t)b * N_NODES + nb + rr) * 64 + c];
        }
        if (t2 < 32) {
            int rr = t2 >> 1, c = t2 & 1;
            tile[sub][rr][c] = x[((size_t)b * N_NODES + nb + rr) * 2 + c];
        }
        __syncthreads();
        if (t2 < C_IN) {
            __half h[16];
#pragma unroll
            for (int rr = 0; rr < 16; rr++) h[rr] = __float2half_rn(tile[sub][rr][t2]);
            size_t off = (size_t)(b * C_IN + t2) * N_NODES + nb;
            *(uint4*)(g_T0 + off)     = *(uint4*)&h[0];
            *(uint4*)(g_T0 + off + 8) = *(uint4*)&h[8];
        }

    } else if (blk < 4160) {                // ---- padT0 ----
        int idx = (blk - 4096) * 256 + t;
        if (idx < (NPAD - BC) * N_NODES / 8) {
            size_t off = (size_t)BC * N_NODES + (size_t)idx * 8;
            *(uint4*)(g_T0 + off) = make_uint4(0, 0, 0, 0);
        }

    } else {                                // ---- wfold ----
        int idx = (blk - 4160) * 256 + t;
        if (idx < C_IN * GATE_OUT) {
            int c = idx / GATE_OUT, o = idx - c * GATE_OUT;
            float w0 = Wg[(c)            * GATE_OUT + o];
            float w1 = Wg[(C_IN + c)     * GATE_OUT + o];
            float w2 = Wg[(2 * C_IN + c) * GATE_OUT + o];
            g_Wg2[(c)            * GATE_OUT + o] = w0 - w2;
            g_Wg2[(C_IN + c)     * GATE_OUT + o] = w1;
            g_Wg2[(2 * C_IN + c) * GATE_OUT + o] = 2.f * w2;
        }
        if (idx < C_IN * UPD_OUT) {
            int c = idx / UPD_OUT, o = idx - c * UPD_OUT;
            float w0 = Wu[(c)            * UPD_OUT + o];
            float w1 = Wu[(C_IN + c)     * UPD_OUT + o];
            float w2 = Wu[(2 * C_IN + c) * UPD_OUT + o];
            g_Wu2[(c)            * UPD_OUT + o] = w0 - w2;
            g_Wu2[(C_IN + c)     * UPD_OUT + o] = w1;
            g_Wu2[(2 * C_IN + c) * UPD_OUT + o] = 2.f * w2;
        }
    }
}

// ---------------- HMMA GEMM: raw D = A @ B^T, fp16 in, fp16 T out ----------
__global__ void __launch_bounds__(256, 1)
mma_gemm(const __half* __restrict__ Ah, const __half* __restrict__ B,
         __half* __restrict__ CT) {
    extern __shared__ char smem[];
    const uint32_t sb = smem_to_u32(smem);
    const int tid = threadIdx.x, wid = tid >> 5, lane = tid & 31;
    const int wr = wid >> 1, wc = wid & 1;            // warp tile: 64x64
    const int m0 = blockIdx.y * 256, n0 = blockIdx.x * 128;

    const __half* srcA = Ah + (size_t)m0 * N_NODES;
    const __half* srcB = B  + (size_t)n0 * N_NODES;

    float acc[4][8][4];
#pragma unroll
    for (int i = 0; i < 4; i++)
#pragma unroll
        for (int j = 0; j < 8; j++)
#pragma unroll
            for (int k = 0; k < 4; k++) acc[i][j][k] = 0.f;

#define COPY_CHUNK(k0, bufi) do {                                             \
        uint32_t _b = sb + (bufi) * 73728;                                    \
        _Pragma("unroll")                                                     \
        for (int _u = 0; _u < 8; _u++) {                                      \
            int _unit = _u * 256 + tid;                                       \
            int _row = _unit >> 3, _q = _unit & 7;                            \
            int _sl = _q >> 1, _hf = _q & 1;                                  \
            cp16(_b + _sl * 12288 + _row * 48 + _hf * 16,                     \
                 srcA + (size_t)_row * N_NODES + (k0) + _sl * 16 + _hf * 8);  \
        }                                                                     \
        _Pragma("unroll")                                                     \
        for (int _u = 0; _u < 4; _u++) {                                      \
            int _unit = _u * 256 + tid;                                       \
            int _row = _unit >> 3, _q = _unit & 7;                            \
            int _sl = _q >> 1, _hf = _q & 1;                                  \
            cp16(_b + 49152 + _sl * 6144 + _row * 48 + _hf * 16,              \
                 srcB + (size_t)_row * N_NODES + (k0) + _sl * 16 + _hf * 8);  \
        }                                                                     \
        asm volatile("cp.async.commit_group;");                               \
    } while (0)

    COPY_CHUNK(0, 0);

    const int NCHUNK = N_NODES / 64;   // 32
    for (int c = 0; c < NCHUNK; c++) {
        int buf = c & 1;
        if (c + 1 < NCHUNK) {
            COPY_CHUNK((c + 1) * 64, buf ^ 1);
            asm volatile("cp.async.wait_group 1;");
        } else {
            asm volatile("cp.async.wait_group 0;");
        }
        __syncthreads();

        uint32_t base = sb + buf * 73728;

#pragma unroll
        for (int s = 0; s < 4; s++) {
            uint32_t a_f[4][4], b_f[4][4];
            int a_roff = (wr * 64 + (lane & 15)) * 48 + (lane >> 4) * 16 + s * 12288;
#pragma unroll
            for (int mt = 0; mt < 4; mt++)
                ldsm4(a_f[mt], base + a_roff + mt * 768);
            int q = lane >> 3, rl = lane & 7;
            int b_roff = (wc * 64 + (q >> 1) * 8 + rl) * 48 + (q & 1) * 16 + s * 6144;
#pragma unroll
            for (int p = 0; p < 4; p++)
                ldsm4(b_f[p], base + 49152 + b_roff + p * 768);
#pragma unroll
            for (int mt = 0; mt < 4; mt++)
#pragma unroll
                for (int nt = 0; nt < 8; nt++)
                    mma_fp16(acc[mt][nt], a_f[mt], &b_f[nt >> 1][(nt & 1) * 2]);
        }
        __syncthreads();
    }
#undef COPY_CHUNK

    const int frow = lane >> 2, fcol = (lane & 3) * 2;
    float* Ct = (float*)smem;          // [128][264] fp32
    __syncthreads();
#pragma unroll
    for (int mt = 0; mt < 4; mt++) {
#pragma unroll
        for (int nt = 0; nt < 8; nt++) {
            int mloc = wr * 64 + mt * 16 + frow;
            int nloc = wc * 64 + nt * 8 + fcol;
            Ct[(nloc + 0) * 264 + mloc]     = acc[mt][nt][0];
            Ct[(nloc + 1) * 264 + mloc]     = acc[mt][nt][1];
            Ct[(nloc + 0) * 264 + mloc + 8] = acc[mt][nt][2];
            Ct[(nloc + 1) * 264 + mloc + 8] = acc[mt][nt][3];
        }
    }
    __syncthreads();
    for (int it = 0; it < 16; it++) {
        int nloc = it * 8 + wid;
#pragma unroll
        for (int j = 0; j < 2; j++) {
            int mloc = lane * 4 + j * 128;
            float4 v = *(float4*)&Ct[nloc * 264 + mloc];
            __half h[4];
            h[0] = __float2half_rn(v.x);
            h[1] = __float2half_rn(v.y);
            h[2] = __float2half_rn(v.z);
            h[3] = __float2half_rn(v.w);
            size_t off = (size_t)(n0 + nloc) * N_NODES + m0 + mloc;
            *(uint2*)(CT + off) = *(uint2*)h;
        }
    }
}

// ---------------- K4: gate via tensor cores --------------------------------
// Block = (b, 128 nodes). A = [k=208][m=128] smem (stride 136 halves) from T
// arrays via contiguous copies; W = [o=128][k=208] fp16 (stride 216 halves).
// 8 warps: wr=wid>>1 (32 m), wc=wid&1 (64 n). sigmoid epilogue; C0T in place.
__global__ void __launch_bounds__(256)
gate_kernel(const float* __restrict__ x, const float* __restrict__ st,
            const float* __restrict__ bg) {
    extern __shared__ char smem[];
    __half* SA = (__half*)smem;                  // 208*136 halves = 56576 B
    __half* SW = (__half*)(smem + 56576);        // 128*216 halves = 55296 B
    const uint32_t sbA = smem_to_u32(SA);
    const uint32_t sbW = smem_to_u32(SW);
    int t = threadIdx.x;
    int b = blockIdx.x >> 4;
    int n0 = (blockIdx.x & 15) * 128;
    const __half* TP[3] = { g_T0, g_T1, g_T2 };

    for (int u = t; u < KPAD * 16; u += 256) {   // A fill
        int k = u >> 4, seg = u & 15;
        uint32_t dst = sbA + k * 272 + seg * 16;
        if (k < IN3) {
            const __half* src = TP[k / C_IN] +
                (size_t)(b * C_IN + k % C_IN) * N_NODES + n0 + seg * 8;
            uint4 v = *(const uint4*)src;
            asm volatile("st.shared.v4.b32 [%0], {%1,%2,%3,%4};"
                         :: "r"(dst), "r"(v.x), "r"(v.y), "r"(v.z), "r"(v.w));
        } else {
            asm volatile("st.shared.v4.b32 [%0], {%1,%1,%1,%1};" :: "r"(dst), "r"(0u));
        }
    }
    for (int idx = t; idx < KPAD * 128; idx += 256) {   // W fill (transpose)
        int k = idx >> 7, o = idx & 127;
        SW[o * 216 + k] = (k < IN3) ? __float2half_rn(g_Wg2[k * GATE_OUT + o])
                                    : __half(0);
    }
    __syncthreads();

    int lane = t & 31, wid = t >> 5;
    int wr = wid >> 1, wc = wid & 1;
    float acc[2][8][4];
#pragma unroll
    for (int i = 0; i < 2; i++)
#pragma unroll
        for (int j = 0; j < 8; j++)
#pragma unroll
            for (int k = 0; k < 4; k++) acc[i][j][k] = 0.f;

    int krow_l = (lane & 7) + ((lane >> 4) << 3);
    int mcol8 = ((lane >> 3) & 1) * 8;
    int q = lane >> 3, rl = lane & 7;

    for (int s = 0; s < KPAD / 16; s++) {
        int k0 = s * 16;
        uint32_t a_f[2][4], b_f[4][4];
#pragma unroll
        for (int mt = 0; mt < 2; mt++) {
            int mbase = wr * 32 + mt * 16 + mcol8;
            ldsm4t(a_f[mt], sbA + (k0 + krow_l) * 272 + mbase * 2);
        }
#pragma unroll
        for (int p = 0; p < 4; p++) {
            int nrow = wc * 64 + p * 16 + (q >> 1) * 8 + rl;
            ldsm4(b_f[p], sbW + nrow * 432 + (k0 + (q & 1) * 8) * 2);
        }
#pragma unroll
        for (int mt = 0; mt < 2; mt++)
#pragma unroll
            for (int nt = 0; nt < 8; nt++)
                mma_fp16(acc[mt][nt], a_f[mt], &b_f[nt >> 1][(nt & 1) * 2]);
    }
    __syncthreads();                 // done reading SA

    int frow = lane >> 2, fcol = (lane & 3) * 2;
    __half* CT = SA;                 // [64][136] staging for z*state
#pragma unroll
    for (int mt = 0; mt < 2; mt++) {
#pragma unroll
        for (int nt = 0; nt < 8; nt++) {
#pragma unroll
            for (int hr = 0; hr < 2; hr++) {
                int mloc = wr * 32 + mt * 16 + frow + hr * 8;
                int row = b * N_NODES + n0 + mloc;
#pragma unroll
                for (int h = 0; h < 2; h++) {
                    int o = wc * 64 + nt * 8 + fcol + h;
                    float v = acc[mt][nt][hr * 2 + h] + bg[o];
                    v = 1.0f / (1.0f + expf(-v));
                    if (o < 64)
                        CT[o * 136 + mloc] = __float2half_rn(v * st[(size_t)row * 64 + o]);
                    else
                        g_r[(size_t)row * 64 + (o - 64)] = v;
                }
            }
        }
    }
    if (t < 128) {                   // x columns of C0T
        int node = n0 + t;
        int row = b * N_NODES + node;
        g_T0[(size_t)(b * C_IN + 0) * N_NODES + node] = __float2half_rn(x[row * 2 + 0]);
        g_T0[(size_t)(b * C_IN + 1) * N_NODES + node] = __float2half_rn(x[row * 2 + 1]);
    }
    __syncthreads();
    for (int j = wid; j < 64; j += 8) {
        uint2 v = *(uint2*)&CT[j * 136 + lane * 4];
        *(uint2*)(g_T0 + (size_t)(b * C_IN + 2 + j) * N_NODES + n0 + lane * 4) = v;
    }
}

// ---------------- K5: update via tensor cores ------------------------------
// Block = (b, 128 nodes). 8 warps: wid = 16-row m tile; n = 64 full.
__global__ void __launch_bounds__(256)
update_kernel(const float* __restrict__ st, const float* __restrict__ bu,
              float* __restrict__ out) {
    extern __shared__ char smem[];
    __half* SA = (__half*)smem;                  // 208*136 = 56576 B
    __half* SW = (__half*)(smem + 56576);        // 64*216 = 27648 B
    const uint32_t sbA = smem_to_u32(SA);
    const uint32_t sbW = smem_to_u32(SW);
    int t = threadIdx.x;
    int b = blockIdx.x >> 4;
    int n0 = (blockIdx.x & 15) * 128;
    const __half* TP[3] = { g_T0, g_T1, g_T2 };

    for (int u = t; u < KPAD * 16; u += 256) {
        int k = u >> 4, seg = u & 15;
        uint32_t dst = sbA + k * 272 + seg * 16;
        if (k < IN3) {
            const __half* src = TP[k / C_IN] +
                (size_t)(b * C_IN + k % C_IN) * N_NODES + n0 + seg * 8;
            uint4 v = *(const uint4*)src;
            asm volatile("st.shared.v4.b32 [%0], {%1,%2,%3,%4};"
                         :: "r"(dst), "r"(v.x), "r"(v.y), "r"(v.z), "r"(v.w));
        } else {
            asm volatile("st.shared.v4.b32 [%0], {%1,%1,%1,%1};" :: "r"(dst), "r"(0u));
        }
    }
    for (int idx = t; idx < KPAD * 64; idx += 256) {
        int k = idx >> 6, o = idx & 63;
        SW[o * 216 + k] = (k < IN3) ? __float2half_rn(g_Wu2[k * UPD_OUT + o])
                                    : __half(0);
    }
    __syncthreads();

    int lane = t & 31, wid = t >> 5;
    float acc[8][4];
#pragma unroll
    for (int j = 0; j < 8; j++)
#pragma unroll
        for (int k = 0; k < 4; k++) acc[j][k] = 0.f;

    int krow_l = (lane & 7) + ((lane >> 4) << 3);
    int mcol8 = ((lane >> 3) & 1) * 8;
    int q = lane >> 3, rl = lane & 7;

    for (int s = 0; s < KPAD / 16; s++) {
        int k0 = s * 16;
        uint32_t a_f[4], b_f[4][4];
        int mbase = wid * 16 + mcol8;
        ldsm4t(a_f, sbA + (k0 + krow_l) * 272 + mbase * 2);
#pragma unroll
        for (int p = 0; p < 4; p++) {
            int nrow = p * 16 + (q >> 1) * 8 + rl;
            ldsm4(b_f[p], sbW + nrow * 432 + (k0 + (q & 1) * 8) * 2);
        }
#pragma unroll
        for (int nt = 0; nt < 8; nt++)
            mma_fp16(acc[nt], a_f, &b_f[nt >> 1][(nt & 1) * 2]);
    }

    int frow = lane >> 2, fcol = (lane & 3) * 2;
#pragma unroll
    for (int nt = 0; nt < 8; nt++) {
#pragma unroll
        for (int hr = 0; hr < 2; hr++) {
            int mloc = wid * 16 + frow + hr * 8;
            int row = b * N_NODES + n0 + mloc;
            float2 ov;
#pragma unroll
            for (int h = 0; h < 2; h++) {
                int o = nt * 8 + fcol + h;
                float hc = tanhf(acc[nt][hr * 2 + h] + bu[o]);
                float rv = g_r[(size_t)row * 64 + o];
                float sv = st[(size_t)row * 64 + o];
                float res = rv * sv + (1.0f - rv) * hc;
                if (h == 0) ov.x = res; else ov.y = res;
            }
            *(float2*)(out + (size_t)row * 64 + nt * 8 + fcol) = ov;
        }
    }
}

// ---------------- launch ----------------------------------------------------
extern "C" void kernel_launch(void* const* d_in, const int* in_sizes, int n_in,
                              void* d_out, int out_size) {
    const float* x  = (const float*)d_in[0];
    const float* st = (const float*)d_in[1];
    const float* E  = (const float*)d_in[2];
    const float* Wg = (const float*)d_in[3];
    const float* bg = (const float*)d_in[4];
    const float* Wu = (const float*)d_in[5];
    const float* bu = (const float*)d_in[6];
    float* out = (float*)d_out;

    __half *pAh, *pT0, *pT1, *pT2;
    cudaGetSymbolAddress((void**)&pAh, g_Ah);
    cudaGetSymbolAddress((void**)&pT0, g_T0);
    cudaGetSymbolAddress((void**)&pT1, g_T1);
    cudaGetSymbolAddress((void**)&pT2, g_T2);

    const int GEMM_SMEM = 2 * 73728;
    const int GATE_SMEM = 56576 + 55296;   // 111872
    const int UPD_SMEM  = 56576 + 27648;   // 84224
    cudaFuncSetAttribute(mma_gemm, cudaFuncAttributeMaxDynamicSharedMemorySize, GEMM_SMEM);
    cudaFuncSetAttribute(gate_kernel, cudaFuncAttributeMaxDynamicSharedMemorySize, GATE_SMEM);
    cudaFuncSetAttribute(update_kernel, cudaFuncAttributeMaxDynamicSharedMemorySize, UPD_SMEM);

    dim3 gg(NPAD / 128, N_NODES / 256);   // (17, 8) = 136 CTAs, single wave

    prep_kernel<<<4193, 256>>>(E, x, st, Wg, Wu);

    // gate gconv (folded): X1T = (A X0)T ; Y2T = (A X1)T
    mma_gemm<<<gg, 256, GEMM_SMEM>>>(pAh, pT0, pT1);
    mma_gemm<<<gg, 256, GEMM_SMEM>>>(pAh, pT1, pT2);

    gate_kernel<<<BATCH * 16, 256, GATE_SMEM>>>(x, st, bg);   // C0T in place

    // update gconv (folded): C1T = (A C0)T ; Y4T = (A C1)T
    mma_gemm<<<gg, 256, GEMM_SMEM>>>(pAh, pT0, pT1);
    mma_gemm<<<gg, 256, GEMM_SMEM>>>(pAh, pT1, pT2);

    update_kernel<<<BATCH * 16, 256, UPD_SMEM>>>(st, bu, out);
}

// round 17
// speedup vs baseline: 1.4971x; 1.0612x over previous
#include <cuda_runtime.h>
#include <cuda_fp16.h>
#include <math.h>
#include <stdint.h>

#define N_NODES 2048
#define BATCH   32
#define HIDDEN  64
#define C_IN    66                 // DIM_IN + HIDDEN
#define BC      2112               // BATCH * C_IN
#define NPAD    2176               // BC padded to multiple of 128
#define IN3     198                // 3 * C_IN
#define KPAD    208                // IN3 padded to multiple of 16
#define GATE_OUT 128
#define UPD_OUT  64

// ---------------- device scratch (static: no allocations allowed) ----------
__device__ __half g_Ah [N_NODES * N_NODES];
__device__ __half g_T0 [NPAD * N_NODES];    // X0T, then (in-place) C0T
__device__ __half g_T1 [NPAD * N_NODES];    // X1T / C1T
__device__ __half g_T2 [NPAD * N_NODES];    // Y2T / Y4T
__device__ float g_r [BATCH * N_NODES * HIDDEN];
__device__ __half g_WgH[GATE_OUT * KPAD];   // folded gate W, [o][k] fp16
__device__ __half g_WuH[UPD_OUT * KPAD];    // folded update W, [o][k] fp16

__device__ __forceinline__ uint32_t smem_to_u32(const void* p) {
    uint32_t a;
    asm("{ .reg .u64 t; cvta.to.shared.u64 t, %1; cvt.u32.u64 %0, t; }" : "=r"(a) : "l"(p));
    return a;
}
__device__ __forceinline__ void mma_fp16(float* c, const uint32_t* a, const uint32_t* b) {
    asm volatile(
        "mma.sync.aligned.m16n8k16.row.col.f32.f16.f16.f32 "
        "{%0,%1,%2,%3}, {%4,%5,%6,%7}, {%8,%9}, {%0,%1,%2,%3};"
        : "+f"(c[0]), "+f"(c[1]), "+f"(c[2]), "+f"(c[3])
        : "r"(a[0]), "r"(a[1]), "r"(a[2]), "r"(a[3]), "r"(b[0]), "r"(b[1]));
}
__device__ __forceinline__ void ldsm4(uint32_t* r, uint32_t addr) {
    asm volatile("ldmatrix.sync.aligned.m8n8.x4.shared.b16 {%0,%1,%2,%3}, [%4];"
                 : "=r"(r[0]), "=r"(r[1]), "=r"(r[2]), "=r"(r[3]) : "r"(addr));
}
__device__ __forceinline__ void ldsm4t(uint32_t* r, uint32_t addr) {
    asm volatile("ldmatrix.sync.aligned.m8n8.x4.trans.shared.b16 {%0,%1,%2,%3}, [%4];"
                 : "=r"(r[0]), "=r"(r[1]), "=r"(r[2]), "=r"(r[3]) : "r"(addr));
}
__device__ __forceinline__ void cp16(uint32_t daddr, const void* g) {
    asm volatile("cp.async.cg.shared.global [%0], [%1], 16;" :: "r"(daddr), "l"(g));
}

// ---------------- K1: fused prep: supports | packT | padT0 | wfold(fp16) ---
__global__ void __launch_bounds__(256)
prep_kernel(const float* __restrict__ E, const float* __restrict__ x,
            const float* __restrict__ st, const float* __restrict__ Wg,
            const float* __restrict__ Wu) {
    int blk = blockIdx.x;
    int t = threadIdx.x;

    if (blk < 2048) {                       // ---- supports ----
        int n = blk;
        float e[10];
#pragma unroll
        for (int c = 0; c < 10; c++) e[c] = E[n * 10 + c];
        float vals[8];
        float vmax = 0.0f;
#pragma unroll
        for (int j = 0; j < 8; j++) {
            int m = j * 256 + t;
            float s = 0.0f;
#pragma unroll
            for (int c = 0; c < 10; c++) s = fmaf(e[c], E[m * 10 + c], s);
            s = fmaxf(s, 0.0f);
            vals[j] = s;
            vmax = fmaxf(vmax, s);
        }
        __shared__ float red[256];
        red[t] = vmax; __syncthreads();
        for (int s = 128; s > 0; s >>= 1) {
            if (t < s) red[t] = fmaxf(red[t], red[t + s]);
            __syncthreads();
        }
        vmax = red[0]; __syncthreads();
        float lsum = 0.0f;
#pragma unroll
        for (int j = 0; j < 8; j++) { vals[j] = expf(vals[j] - vmax); lsum += vals[j]; }
        red[t] = lsum; __syncthreads();
        for (int s = 128; s > 0; s >>= 1) {
            if (t < s) red[t] += red[t + s];
            __syncthreads();
        }
        float inv = 1.0f / red[0];
#pragma unroll
        for (int j = 0; j < 8; j++)
            g_Ah[(size_t)n * N_NODES + j * 256 + t] = __float2half_rn(vals[j] * inv);

    } else if (blk < 4096) {                // ---- packT ----
        __shared__ float tile[2][16][68];
        int p = blk - 2048;
        int b = p >> 6;
        int n0 = (p & 63) * 32;
        int sub = t >> 7;
        int t2 = t & 127;
        int nb = n0 + sub * 16;

        for (int idx = t2; idx < 1024; idx += 128) {
            int rr = idx >> 6, c = idx & 63;
            tile[sub][rr][2 + c] = st[((size_t)b * N_NODES + nb + rr) * 64 + c];
        }
        if (t2 < 32) {
            int rr = t2 >> 1, c = t2 & 1;
            tile[sub][rr][c] = x[((size_t)b * N_NODES + nb + rr) * 2 + c];
        }
        __syncthreads();
        if (t2 < C_IN) {
            __half h[16];
#pragma unroll
            for (int rr = 0; rr < 16; rr++) h[rr] = __float2half_rn(tile[sub][rr][t2]);
            size_t off = (size_t)(b * C_IN + t2) * N_NODES + nb;
            *(uint4*)(g_T0 + off)     = *(uint4*)&h[0];
            *(uint4*)(g_T0 + off + 8) = *(uint4*)&h[8];
        }

    } else if (blk < 4160) {                // ---- padT0 ----
        int idx = (blk - 4096) * 256 + t;
        if (idx < (NPAD - BC) * N_NODES / 8) {
            size_t off = (size_t)BC * N_NODES + (size_t)idx * 8;
            *(uint4*)(g_T0 + off) = make_uint4(0, 0, 0, 0);
        }

    } else if (blk < 4264) {                // ---- wfold gate -> fp16 [o][k] -
        int idx = (blk - 4160) * 256 + t;   // 128 * 208 = 26624
        if (idx < GATE_OUT * KPAD) {
            int o = idx / KPAD, k = idx - o * KPAD;
            float w = 0.f;
            if (k < C_IN)            w = Wg[k * GATE_OUT + o] - Wg[(2 * C_IN + k) * GATE_OUT + o];
            else if (k < 2 * C_IN)   w = Wg[k * GATE_OUT + o];
            else if (k < IN3)        w = 2.f * Wg[k * GATE_OUT + o];
            g_WgH[idx] = __float2half_rn(w);
        }

    } else {                                // ---- wfold update -> fp16 ------
        int idx = (blk - 4264) * 256 + t;   // 64 * 208 = 13312
        if (idx < UPD_OUT * KPAD) {
            int o = idx / KPAD, k = idx - o * KPAD;
            float w = 0.f;
            if (k < C_IN)            w = Wu[k * UPD_OUT + o] - Wu[(2 * C_IN + k) * UPD_OUT + o];
            else if (k < 2 * C_IN)   w = Wu[k * UPD_OUT + o];
            else if (k < IN3)        w = 2.f * Wu[k * UPD_OUT + o];
            g_WuH[idx] = __float2half_rn(w);
        }
    }
}

// ---------------- HMMA GEMM: raw D = A @ B^T, fp16 in, fp16 T out ----------
__global__ void __launch_bounds__(256, 1)
mma_gemm(const __half* __restrict__ Ah, const __half* __restrict__ B,
         __half* __restrict__ CT) {
    extern __shared__ char smem[];
    const uint32_t sb = smem_to_u32(smem);
    const int tid = threadIdx.x, wid = tid >> 5, lane = tid & 31;
    const int wr = wid >> 1, wc = wid & 1;            // warp tile: 64x64
    const int m0 = blockIdx.y * 256, n0 = blockIdx.x * 128;

    const __half* srcA = Ah + (size_t)m0 * N_NODES;
    const __half* srcB = B  + (size_t)n0 * N_NODES;

    float acc[4][8][4];
#pragma unroll
    for (int i = 0; i < 4; i++)
#pragma unroll
        for (int j = 0; j < 8; j++)
#pragma unroll
            for (int k = 0; k < 4; k++) acc[i][j][k] = 0.f;

#define COPY_CHUNK(k0, bufi) do {                                             \
        uint32_t _b = sb + (bufi) * 73728;                                    \
        _Pragma("unroll")                                                     \
        for (int _u = 0; _u < 8; _u++) {                                      \
            int _unit = _u * 256 + tid;                                       \
            int _row = _unit >> 3, _q = _unit & 7;                            \
            int _sl = _q >> 1, _hf = _q & 1;                                  \
            cp16(_b + _sl * 12288 + _row * 48 + _hf * 16,                     \
                 srcA + (size_t)_row * N_NODES + (k0) + _sl * 16 + _hf * 8);  \
        }                                                                     \
        _Pragma("unroll")                                                     \
        for (int _u = 0; _u < 4; _u++) {                                      \
            int _unit = _u * 256 + tid;                                       \
            int _row = _unit >> 3, _q = _unit & 7;                            \
            int _sl = _q >> 1, _hf = _q & 1;                                  \
            cp16(_b + 49152 + _sl * 6144 + _row * 48 + _hf * 16,              \
                 srcB + (size_t)_row * N_NODES + (k0) + _sl * 16 + _hf * 8);  \
        }                                                                     \
        asm volatile("cp.async.commit_group;");                               \
    } while (0)

    COPY_CHUNK(0, 0);

    const int NCHUNK = N_NODES / 64;   // 32
    for (int c = 0; c < NCHUNK; c++) {
        int buf = c & 1;
        if (c + 1 < NCHUNK) {
            COPY_CHUNK((c + 1) * 64, buf ^ 1);
            asm volatile("cp.async.wait_group 1;");
        } else {
            asm volatile("cp.async.wait_group 0;");
        }
        __syncthreads();

        uint32_t base = sb + buf * 73728;

#pragma unroll
        for (int s = 0; s < 4; s++) {
            uint32_t a_f[4][4], b_f[4][4];
            int a_roff = (wr * 64 + (lane & 15)) * 48 + (lane >> 4) * 16 + s * 12288;
#pragma unroll
            for (int mt = 0; mt < 4; mt++)
                ldsm4(a_f[mt], base + a_roff + mt * 768);
            int q = lane >> 3, rl = lane & 7;
            int b_roff = (wc * 64 + (q >> 1) * 8 + rl) * 48 + (q & 1) * 16 + s * 6144;
#pragma unroll
            for (int p = 0; p < 4; p++)
                ldsm4(b_f[p], base + 49152 + b_roff + p * 768);
#pragma unroll
            for (int mt = 0; mt < 4; mt++)
#pragma unroll
                for (int nt = 0; nt < 8; nt++)
                    mma_fp16(acc[mt][nt], a_f[mt], &b_f[nt >> 1][(nt & 1) * 2]);
        }
        __syncthreads();
    }
#undef COPY_CHUNK

    const int frow = lane >> 2, fcol = (lane & 3) * 2;
    float* Ct = (float*)smem;          // [128][264] fp32
    __syncthreads();
#pragma unroll
    for (int mt = 0; mt < 4; mt++) {
#pragma unroll
        for (int nt = 0; nt < 8; nt++) {
            int mloc = wr * 64 + mt * 16 + frow;
            int nloc = wc * 64 + nt * 8 + fcol;
            Ct[(nloc + 0) * 264 + mloc]     = acc[mt][nt][0];
            Ct[(nloc + 1) * 264 + mloc]     = acc[mt][nt][1];
            Ct[(nloc + 0) * 264 + mloc + 8] = acc[mt][nt][2];
            Ct[(nloc + 1) * 264 + mloc + 8] = acc[mt][nt][3];
        }
    }
    __syncthreads();
    for (int it = 0; it < 16; it++) {
        int nloc = it * 8 + wid;
#pragma unroll
        for (int j = 0; j < 2; j++) {
            int mloc = lane * 4 + j * 128;
            float4 v = *(float4*)&Ct[nloc * 264 + mloc];
            __half h[4];
            h[0] = __float2half_rn(v.x);
            h[1] = __float2half_rn(v.y);
            h[2] = __float2half_rn(v.z);
            h[3] = __float2half_rn(v.w);
            size_t off = (size_t)(n0 + nloc) * N_NODES + m0 + mloc;
            *(uint2*)(CT + off) = *(uint2*)h;
        }
    }
}

// ---------------- K4: gate via tensor cores --------------------------------
// Block = (b, 128 nodes). A = [k=208][m=128] smem (stride 136 halves);
// W = [o=128][k=208] fp16 (stride 208 halves), bulk-copied from g_WgH.
__global__ void __launch_bounds__(256)
gate_kernel(const float* __restrict__ x, const float* __restrict__ st,
            const float* __restrict__ bg) {
    extern __shared__ char smem[];
    __half* SA = (__half*)smem;                  // 208*136 halves = 56576 B
    __half* SW = (__half*)(smem + 56576);        // 128*208 halves = 53248 B
    const uint32_t sbA = smem_to_u32(SA);
    const uint32_t sbW = smem_to_u32(SW);
    int t = threadIdx.x;
    int b = blockIdx.x >> 4;
    int n0 = (blockIdx.x & 15) * 128;
    const __half* TP[3] = { g_T0, g_T1, g_T2 };

    for (int u = t; u < KPAD * 16; u += 256) {   // A fill
        int k = u >> 4, seg = u & 15;
        uint32_t dst = sbA + k * 272 + seg * 16;
        if (k < IN3) {
            cp16(dst, TP[k / C_IN] +
                 (size_t)(b * C_IN + k % C_IN) * N_NODES + n0 + seg * 8);
        } else {
            asm volatile("st.shared.v4.b32 [%0], {%1,%1,%1,%1};" :: "r"(dst), "r"(0u));
        }
    }
    for (int u = t; u < GATE_OUT * KPAD / 8; u += 256)   // W fill: bulk copy
        cp16(sbW + u * 16, g_WgH + (size_t)u * 8);
    asm volatile("cp.async.commit_group;");
    asm volatile("cp.async.wait_group 0;");
    __syncthreads();

    int lane = t & 31, wid = t >> 5;
    int wr = wid >> 1, wc = wid & 1;
    float acc[2][8][4];
#pragma unroll
    for (int i = 0; i < 2; i++)
#pragma unroll
        for (int j = 0; j < 8; j++)
#pragma unroll
            for (int k = 0; k < 4; k++) acc[i][j][k] = 0.f;

    int krow_l = (lane & 7) + ((lane >> 4) << 3);
    int mcol8 = ((lane >> 3) & 1) * 8;
    int q = lane >> 3, rl = lane & 7;

    for (int s = 0; s < KPAD / 16; s++) {
        int k0 = s * 16;
        uint32_t a_f[2][4], b_f[4][4];
#pragma unroll
        for (int mt = 0; mt < 2; mt++) {
            int mbase = wr * 32 + mt * 16 + mcol8;
            ldsm4t(a_f[mt], sbA + (k0 + krow_l) * 272 + mbase * 2);
        }
#pragma unroll
        for (int p = 0; p < 4; p++) {
            int nrow = wc * 64 + p * 16 + (q >> 1) * 8 + rl;
            ldsm4(b_f[p], sbW + nrow * 416 + (k0 + (q & 1) * 8) * 2);
        }
#pragma unroll
        for (int mt = 0; mt < 2; mt++)
#pragma unroll
            for (int nt = 0; nt < 8; nt++)
                mma_fp16(acc[mt][nt], a_f[mt], &b_f[nt >> 1][(nt & 1) * 2]);
    }
    __syncthreads();                 // done reading SA

    int frow = lane >> 2, fcol = (lane & 3) * 2;
    __half* CT = SA;                 // [64][136] staging for z*state
#pragma unroll
    for (int mt = 0; mt < 2; mt++) {
#pragma unroll
        for (int nt = 0; nt < 8; nt++) {
#pragma unroll
            for (int hr = 0; hr < 2; hr++) {
                int mloc = wr * 32 + mt * 16 + frow + hr * 8;
                int row = b * N_NODES + n0 + mloc;
#pragma unroll
                for (int h = 0; h < 2; h++) {
                    int o = wc * 64 + nt * 8 + fcol + h;
                    float v = acc[mt][nt][hr * 2 + h] + bg[o];
                    v = 1.0f / (1.0f + expf(-v));
                    if (o < 64)
                        CT[o * 136 + mloc] = __float2half_rn(v * st[(size_t)row * 64 + o]);
                    else
                        g_r[(size_t)row * 64 + (o - 64)] = v;
                }
            }
        }
    }
    if (t < 128) {                   // x columns of C0T
        int node = n0 + t;
        int row = b * N_NODES + node;
        g_T0[(size_t)(b * C_IN + 0) * N_NODES + node] = __float2half_rn(x[row * 2 + 0]);
        g_T0[(size_t)(b * C_IN + 1) * N_NODES + node] = __float2half_rn(x[row * 2 + 1]);
    }
    __syncthreads();
    for (int j = wid; j < 64; j += 8) {
        uint2 v = *(uint2*)&CT[j * 136 + lane * 4];
        *(uint2*)(g_T0 + (size_t)(b * C_IN + 2 + j) * N_NODES + n0 + lane * 4) = v;
    }
}

// ---------------- K5: update via tensor cores ------------------------------
__global__ void __launch_bounds__(256)
update_kernel(const float* __restrict__ st, const float* __restrict__ bu,
              float* __restrict__ out) {
    extern __shared__ char smem[];
    __half* SA = (__half*)smem;                  // 208*136 = 56576 B
    __half* SW = (__half*)(smem + 56576);        // 64*208 = 26624 B
    const uint32_t sbA = smem_to_u32(SA);
    const uint32_t sbW = smem_to_u32(SW);
    int t = threadIdx.x;
    int b = blockIdx.x >> 4;
    int n0 = (blockIdx.x & 15) * 128;
    const __half* TP[3] = { g_T0, g_T1, g_T2 };

    for (int u = t; u < KPAD * 16; u += 256) {
        int k = u >> 4, seg = u & 15;
        uint32_t dst = sbA + k * 272 + seg * 16;
        if (k < IN3) {
            cp16(dst, TP[k / C_IN] +
                 (size_t)(b * C_IN + k % C_IN) * N_NODES + n0 + seg * 8);
        } else {
            asm volatile("st.shared.v4.b32 [%0], {%1,%1,%1,%1};" :: "r"(dst), "r"(0u));
        }
    }
    for (int u = t; u < UPD_OUT * KPAD / 8; u += 256)
        cp16(sbW + u * 16, g_WuH + (size_t)u * 8);
    asm volatile("cp.async.commit_group;");
    asm volatile("cp.async.wait_group 0;");
    __syncthreads();

    int lane = t & 31, wid = t >> 5;
    float acc[8][4];
#pragma unroll
    for (int j = 0; j < 8; j++)
#pragma unroll
        for (int k = 0; k < 4; k++) acc[j][k] = 0.f;

    int krow_l = (lane & 7) + ((lane >> 4) << 3);
    int mcol8 = ((lane >> 3) & 1) * 8;
    int q = lane >> 3, rl = lane & 7;

    for (int s = 0; s < KPAD / 16; s++) {
        int k0 = s * 16;
        uint32_t a_f[4], b_f[4][4];
        int mbase = wid * 16 + mcol8;
        ldsm4t(a_f, sbA + (k0 + krow_l) * 272 + mbase * 2);
#pragma unroll
        for (int p = 0; p < 4; p++) {
            int nrow = p * 16 + (q >> 1) * 8 + rl;
            ldsm4(b_f[p], sbW + nrow * 416 + (k0 + (q & 1) * 8) * 2);
        }
#pragma unroll
        for (int nt = 0; nt < 8; nt++)
            mma_fp16(acc[nt], a_f, &b_f[nt >> 1][(nt & 1) * 2]);
    }

    int frow = lane >> 2, fcol = (lane & 3) * 2;
#pragma unroll
    for (int nt = 0; nt < 8; nt++) {
#pragma unroll
        for (int hr = 0; hr < 2; hr++) {
            int mloc = wid * 16 + frow + hr * 8;
            int row = b * N_NODES + n0 + mloc;
            float2 ov;
#pragma unroll
            for (int h = 0; h < 2; h++) {
                int o = nt * 8 + fcol + h;
                float hc = tanhf(acc[nt][hr * 2 + h] + bu[o]);
                float rv = g_r[(size_t)row * 64 + o];
                float sv = st[(size_t)row * 64 + o];
                float res = rv * sv + (1.0f - rv) * hc;
                if (h == 0) ov.x = res; else ov.y = res;
            }
            *(float2*)(out + (size_t)row * 64 + nt * 8 + fcol) = ov;
        }
    }
}

// ---------------- launch ----------------------------------------------------
extern "C" void kernel_launch(void* const* d_in, const int* in_sizes, int n_in,
                              void* d_out, int out_size) {
    const float* x  = (const float*)d_in[0];
    const float* st = (const float*)d_in[1];
    const float* E  = (const float*)d_in[2];
    const float* Wg = (const float*)d_in[3];
    const float* bg = (const float*)d_in[4];
    const float* Wu = (const float*)d_in[5];
    const float* bu = (const float*)d_in[6];
    float* out = (float*)d_out;

    __half *pAh, *pT0, *pT1, *pT2;
    cudaGetSymbolAddress((void**)&pAh, g_Ah);
    cudaGetSymbolAddress((void**)&pT0, g_T0);
    cudaGetSymbolAddress((void**)&pT1, g_T1);
    cudaGetSymbolAddress((void**)&pT2, g_T2);

    const int GEMM_SMEM = 2 * 73728;
    const int GATE_SMEM = 56576 + 53248;   // 109824
    const int UPD_SMEM  = 56576 + 26624;   // 83200
    cudaFuncSetAttribute(mma_gemm, cudaFuncAttributeMaxDynamicSharedMemorySize, GEMM_SMEM);
    cudaFuncSetAttribute(gate_kernel, cudaFuncAttributeMaxDynamicSharedMemorySize, GATE_SMEM);
    cudaFuncSetAttribute(update_kernel, cudaFuncAttributeMaxDynamicSharedMemorySize, UPD_SMEM);

    dim3 gg(NPAD / 128, N_NODES / 256);   // (17, 8) = 136 CTAs, single wave

    prep_kernel<<<4316, 256>>>(E, x, st, Wg, Wu);

    // gate gconv (folded): X1T = (A X0)T ; Y2T = (A X1)T
    mma_gemm<<<gg, 256, GEMM_SMEM>>>(pAh, pT0, pT1);
    mma_gemm<<<gg, 256, GEMM_SMEM>>>(pAh, pT1, pT2);

    gate_kernel<<<BATCH * 16, 256, GATE_SMEM>>>(x, st, bg);   // C0T in place

    // update gconv (folded): C1T = (A C0)T ; Y4T = (A C1)T
    mma_gemm<<<gg, 256, GEMM_SMEM>>>(pAh, pT0, pT1);
    mma_gemm<<<gg, 256, GEMM_SMEM>>>(pAh, pT1, pT2);

    update_kernel<<<BATCH * 16, 256, UPD_SMEM>>>(st, bu, out);
}